// round 3
// baseline (speedup 1.0000x reference)
#include <cuda_runtime.h>
#include <cuda_bf16.h>

// Shapes (fixed for this problem)
#define NB 4
#define NQ 512
#define NK 512
#define ND 256
#define NH 256

#define STRIDE 260            // smem row stride (floats): 1040B; 1040 mod 128 = 16 -> conflict-free LDS.128

// Scratch: projected queries/keys (B*Q x H) and (B*K x H)
__device__ float g_qh[NB * NQ * NH];
__device__ float g_kh[NB * NK * NH];

__device__ __forceinline__ float tanh_ap(float x) {
    float y;
    asm("tanh.approx.f32 %0, %1;" : "=f"(y) : "f"(x));
    return y;
}

// ---------------------------------------------------------------------------
// Projection GEMM: C[2048x256] = A[2048x256] @ W[256x256]
// blockIdx.z = 0 -> (queries, Wq, g_qh), 1 -> (keys, Wk, g_kh)
// 64x64 output tile per block, BK=16, 256 threads, 4x4 micro-tile.
// ---------------------------------------------------------------------------
__global__ __launch_bounds__(256) void proj_kernel(
    const float* __restrict__ Aq, const float* __restrict__ Wq,
    const float* __restrict__ Ak, const float* __restrict__ Wk)
{
    const float* A; const float* W; float* C;
    if (blockIdx.z == 0) { A = Aq; W = Wq; C = g_qh; }
    else                 { A = Ak; W = Wk; C = g_kh; }

    __shared__ float As[16][68];   // [k][m], transposed on store
    __shared__ float Bs[16][68];   // [k][n]

    const int t    = threadIdx.x;
    const int row0 = blockIdx.y * 64;
    const int col0 = blockIdx.x * 64;
    const int ty   = t >> 4;
    const int tx   = t & 15;

    float acc[4][4] = {};

    for (int k0 = 0; k0 < ND; k0 += 16) {
        {
            int r  = t >> 2;
            int c4 = (t & 3) * 4;
            float4 v = *(const float4*)&A[(row0 + r) * ND + k0 + c4];
            As[c4 + 0][r] = v.x;
            As[c4 + 1][r] = v.y;
            As[c4 + 2][r] = v.z;
            As[c4 + 3][r] = v.w;
        }
        {
            int r  = t >> 4;
            int c4 = (t & 15) * 4;
            *(float4*)&Bs[r][c4] = *(const float4*)&W[(k0 + r) * NH + col0 + c4];
        }
        __syncthreads();
        #pragma unroll
        for (int kk = 0; kk < 16; kk++) {
            float4 av = *(float4*)&As[kk][ty * 4];
            float4 bv = *(float4*)&Bs[kk][tx * 4];
            float a_[4] = {av.x, av.y, av.z, av.w};
            float b_[4] = {bv.x, bv.y, bv.z, bv.w};
            #pragma unroll
            for (int i = 0; i < 4; i++)
                #pragma unroll
                for (int j = 0; j < 4; j++)
                    acc[i][j] += a_[i] * b_[j];
        }
        __syncthreads();
    }

    #pragma unroll
    for (int i = 0; i < 4; i++) {
        float4 v = make_float4(acc[i][0], acc[i][1], acc[i][2], acc[i][3]);
        *(float4*)&C[(row0 + ty * 4 + i) * NH + col0 + tx * 4] = v;
    }
}

// ---------------------------------------------------------------------------
// Fused scores (tanh additive) + masked softmax + attn @ values.
// 512 blocks x 128 threads; 4 warps = 4 queries of ONE batch.
// Batch-interleaved mapping: b = blockIdx & 3 (mixes valid_lens within waves).
// Phase A: 32-key kh tiles in smem; lane = key; raw scores -> attn_s (smem).
// Phase B: softmax from smem with predicate masking (no sc[] register array,
//          no forced tile-loop unroll -> small SASS, runtime loops).
// Phase C: 16-key values tiles; 8 outputs/thread (2 float4).
// ---------------------------------------------------------------------------
__global__ __launch_bounds__(128, 4) void attn_kernel(
    const float* __restrict__ values,
    const float* __restrict__ wv,
    const int*   __restrict__ valid_lens,
    float*       __restrict__ out)
{
    __shared__ float sbuf[32 * STRIDE];    // 33280 B: kh tiles (A) / values tiles (C)
    __shared__ float attn_s[4 * NK];       // 8192 B: raw scores -> unnormalized exp
    __shared__ float s_qh[4 * NH];         // 4096 B
    __shared__ float s_wv[NH];             // 1024 B

    const int t    = threadIdx.x;
    const int w    = t >> 5;               // warp = query-in-block
    const int lane = t & 31;
    const int b    = blockIdx.x & 3;       // batch-interleaved
    const int qblk = blockIdx.x >> 2;      // 0..127
    const int q    = qblk * 4 + w;         // query index within batch
    const int vl   = valid_lens[b];        // uniform across block

    // ---------------- prologue: stage qh rows + wv ----------------
    #pragma unroll
    for (int rr = 0; rr < 2; rr++) {
        int i = t + 128 * rr;              // 0..255 float4 slots (4 rows x 64)
        int r = i >> 6;
        int c = (i & 63) * 4;
        *(float4*)&s_qh[r * NH + c] =
            *(const float4*)&g_qh[(b * NQ + qblk * 4 + r) * NH + c];
    }
    if (t < 64) *(float4*)&s_wv[t * 4] = *(const float4*)&wv[t * 4];
    __syncthreads();

    // ---------------- Phase A: scores -> attn_s ----------------
    const float* khb = &g_kh[(b * NK) * NH];
    const float* myq = &s_qh[w * NH];
    const int nTilesA = (vl + 31) >> 5;    // uniform

    for (int tile = 0; tile < nTilesA; ++tile) {
        // load kh tile: 32 keys x 256 h  (2048 float4, 16 per thread)
        #pragma unroll
        for (int r = 0; r < 16; ++r) {
            int i  = t + 128 * r;
            int k  = i >> 6;
            int h4 = (i & 63) * 4;
            *(float4*)&sbuf[k * STRIDE + h4] =
                *(const float4*)&khb[(tile * 32 + k) * NH + h4];
        }
        __syncthreads();

        float acc = 0.f;
        const float* myk = &sbuf[lane * STRIDE];
        #pragma unroll 4
        for (int h = 0; h < NH; h += 4) {
            float4 kv  = *(const float4*)&myk[h];
            float4 qv  = *(const float4*)&myq[h];    // broadcast
            float4 wv4 = *(const float4*)&s_wv[h];   // broadcast
            acc += wv4.x * tanh_ap(qv.x + kv.x);
            acc += wv4.y * tanh_ap(qv.y + kv.y);
            acc += wv4.z * tanh_ap(qv.z + kv.z);
            acc += wv4.w * tanh_ap(qv.w + kv.w);
        }
        attn_s[w * NK + tile * 32 + lane] = acc;     // raw score
        __syncthreads();
    }

    // ---------------- Phase B: masked softmax (smem + shuffles) ----------------
    // Reads past covered tiles never happen masked-wrong: predicate selects -1e6
    // for k >= vl (uninitialized smem beyond vl is never used).
    float mx = -1.0e30f;
    float sc[16];
    #pragma unroll
    for (int i = 0; i < 16; i++) {
        int k = i * 32 + lane;
        float v = attn_s[w * NK + k];
        v = (k < vl) ? v : -1.0e6f;
        sc[i] = v;
        mx = fmaxf(mx, v);
    }
    #pragma unroll
    for (int o = 16; o > 0; o >>= 1)
        mx = fmaxf(mx, __shfl_xor_sync(0xffffffffu, mx, o));

    float sum = 0.f;
    #pragma unroll
    for (int i = 0; i < 16; i++) {
        float e = __expf(sc[i] - mx);                // masked -> exact 0 (underflow)
        sum += e;
        attn_s[w * NK + i * 32 + lane] = e;          // unnormalized (own row: warp-local)
    }
    #pragma unroll
    for (int o = 16; o > 0; o >>= 1)
        sum += __shfl_xor_sync(0xffffffffu, sum, o);
    const float inv = 1.0f / sum;

    // ---------------- Phase C: out = attn @ values ----------------
    float4 o0 = make_float4(0.f, 0.f, 0.f, 0.f);
    float4 o1 = make_float4(0.f, 0.f, 0.f, 0.f);
    const int nTilesC = (vl + 15) >> 4;
    const float* vb = &values[(b * NK) * ND];

    for (int tile = 0; tile < nTilesC; ++tile) {
        __syncthreads();                   // prior sbuf reads done (incl. phase A)
        // load values tile: 16 keys x 256 d (1024 float4, 8 per thread)
        #pragma unroll
        for (int r = 0; r < 8; ++r) {
            int i  = t + 128 * r;
            int k  = i >> 6;
            int h4 = (i & 63) * 4;
            *(float4*)&sbuf[k * STRIDE + h4] =
                *(const float4*)&vb[(tile * 16 + k) * ND + h4];
        }
        __syncthreads();

        #pragma unroll 4
        for (int kk = 0; kk < 16; ++kk) {
            float a = attn_s[w * NK + tile * 16 + kk];        // broadcast (own row)
            float4 v0 = *(const float4*)&sbuf[kk * STRIDE + 4 * lane];
            float4 v1 = *(const float4*)&sbuf[kk * STRIDE + 128 + 4 * lane];
            o0.x += a * v0.x; o0.y += a * v0.y; o0.z += a * v0.z; o0.w += a * v0.w;
            o1.x += a * v1.x; o1.y += a * v1.y; o1.z += a * v1.z; o1.w += a * v1.w;
        }
    }

    o0.x *= inv; o0.y *= inv; o0.z *= inv; o0.w *= inv;
    o1.x *= inv; o1.y *= inv; o1.z *= inv; o1.w *= inv;
    const int qrow = b * NQ + q;
    *(float4*)&out[qrow * ND + 4 * lane]       = o0;
    *(float4*)&out[qrow * ND + 128 + 4 * lane] = o1;
}

// ---------------------------------------------------------------------------
extern "C" void kernel_launch(void* const* d_in, const int* in_sizes, int n_in,
                              void* d_out, int out_size)
{
    const float* queries = (const float*)d_in[0];  // (B,Q,D)
    const float* keys    = (const float*)d_in[1];  // (B,K,D)
    const float* values  = (const float*)d_in[2];  // (B,K,D)
    const float* Wq      = (const float*)d_in[3];  // (D,H)
    const float* Wk      = (const float*)d_in[4];  // (D,H)
    const float* wv      = (const float*)d_in[5];  // (H,)
    const int*   vlen    = (const int*)d_in[6];    // (B,) int32
    float* out = (float*)d_out;                    // (B,Q,D)

    (void)in_sizes; (void)n_in; (void)out_size;

    dim3 pgrid(NH / 64, (NB * NQ) / 64, 2);        // 4 x 32 x 2
    proj_kernel<<<pgrid, 256>>>(queries, Wq, keys, Wk);

    attn_kernel<<<(NB * NQ) / 4, 128>>>(values, wv, vlen, out);
}

// round 4
// speedup vs baseline: 1.0036x; 1.0036x over previous
#include <cuda_runtime.h>
#include <cuda_bf16.h>

// Shapes (fixed for this problem)
#define NB 4
#define NQ 512
#define NK 512
#define ND 256
#define NH 256

#define STRIDE 260   // smem row stride (floats); 260 mod 32 = 4 -> conflict-free per 8-lane LDS.128 phase

// Scratch: projected queries/keys (B*Q x H) and (B*K x H)
__device__ float g_qh[NB * NQ * NH];
__device__ float g_kh[NB * NK * NH];

__device__ __forceinline__ float tanh_ap(float x) {
    float y;
    asm("tanh.approx.f32 %0, %1;" : "=f"(y) : "f"(x));
    return y;
}

// ---------------------------------------------------------------------------
// Projection GEMM: C[2048x256] = A[2048x256] @ W[256x256]
// blockIdx.z = 0 -> (queries, Wq, g_qh), 1 -> (keys, Wk, g_kh)
// 64x64 output tile per block, BK=16, 256 threads, 4x4 micro-tile.
// ---------------------------------------------------------------------------
__global__ __launch_bounds__(256) void proj_kernel(
    const float* __restrict__ Aq, const float* __restrict__ Wq,
    const float* __restrict__ Ak, const float* __restrict__ Wk)
{
    const float* A; const float* W; float* C;
    if (blockIdx.z == 0) { A = Aq; W = Wq; C = g_qh; }
    else                 { A = Ak; W = Wk; C = g_kh; }

    __shared__ float As[16][68];   // [k][m], transposed on store
    __shared__ float Bs[16][68];   // [k][n]

    const int t    = threadIdx.x;
    const int row0 = blockIdx.y * 64;
    const int col0 = blockIdx.x * 64;
    const int ty   = t >> 4;
    const int tx   = t & 15;

    float acc[4][4] = {};

    for (int k0 = 0; k0 < ND; k0 += 16) {
        {
            int r  = t >> 2;
            int c4 = (t & 3) * 4;
            float4 v = *(const float4*)&A[(row0 + r) * ND + k0 + c4];
            As[c4 + 0][r] = v.x;
            As[c4 + 1][r] = v.y;
            As[c4 + 2][r] = v.z;
            As[c4 + 3][r] = v.w;
        }
        {
            int r  = t >> 4;
            int c4 = (t & 15) * 4;
            *(float4*)&Bs[r][c4] = *(const float4*)&W[(k0 + r) * NH + col0 + c4];
        }
        __syncthreads();
        #pragma unroll
        for (int kk = 0; kk < 16; kk++) {
            float4 av = *(float4*)&As[kk][ty * 4];
            float4 bv = *(float4*)&Bs[kk][tx * 4];
            float a_[4] = {av.x, av.y, av.z, av.w};
            float b_[4] = {bv.x, bv.y, bv.z, bv.w};
            #pragma unroll
            for (int i = 0; i < 4; i++)
                #pragma unroll
                for (int j = 0; j < 4; j++)
                    acc[i][j] += a_[i] * b_[j];
        }
        __syncthreads();
    }

    #pragma unroll
    for (int i = 0; i < 4; i++) {
        float4 v = make_float4(acc[i][0], acc[i][1], acc[i][2], acc[i][3]);
        *(float4*)&C[(row0 + ty * 4 + i) * NH + col0 + tx * 4] = v;
    }
}

// ---------------------------------------------------------------------------
// Fused scores + masked softmax + attn @ values.
// 512 blocks x 256 threads = 8 warps = 4 queries x 2 slices (one batch/block,
// b = blockIdx & 3 interleaved). TWO warps per query doubles warp-level
// parallelism (4096 warps total vs 2048) -> ~28 warps/SM in the single wave.
//
// Phase A: 32-key kh tiles in smem; warp (q, slice): keys slice*16+(lane&15),
//          h-half (lane>>4)*128; score combined with shfl_xor(16).
// Phase B: even warps do their query's softmax from smem (2 passes, no sc[16]
//          register array); 1/sum -> s_inv[].
// Phase C: 16-key values tiles; warp (q, d-half); float4 accumulator.
// ---------------------------------------------------------------------------
__global__ __launch_bounds__(256, 4) void attn_kernel(
    const float* __restrict__ values,
    const float* __restrict__ wv,
    const int*   __restrict__ valid_lens,
    float*       __restrict__ out)
{
    __shared__ float sbuf[32 * STRIDE];    // 33280 B: kh tiles (A) / values tiles (C)
    __shared__ float attn_s[4 * NK];       // 8192 B: raw scores -> unnormalized exp
    __shared__ float s_qh[4 * NH];         // 4096 B
    __shared__ float s_wv[NH];             // 1024 B
    __shared__ float s_inv[4];

    const int t     = threadIdx.x;
    const int w     = t >> 5;
    const int lane  = t & 31;
    const int q     = w >> 1;              // query-in-block 0..3
    const int slice = w & 1;               // key/d half
    const int b     = blockIdx.x & 3;      // batch-interleaved
    const int qblk  = blockIdx.x >> 2;     // 0..127
    const int vl    = valid_lens[b];       // uniform across block

    // ---------------- prologue: stage qh rows + wv ----------------
    {
        int r = t >> 6;                    // 4 rows x 64 float4 slots
        int c = (t & 63) * 4;
        *(float4*)&s_qh[r * NH + c] =
            *(const float4*)&g_qh[(b * NQ + qblk * 4 + r) * NH + c];
    }
    if (t < 64) *(float4*)&s_wv[t * 4] = *(const float4*)&wv[t * 4];
    __syncthreads();

    // ---------------- Phase A: scores -> attn_s ----------------
    const float* khb = &g_kh[(b * NK) * NH];
    const int row    = slice * 16 + (lane & 15);   // key-in-tile this lane scores
    const int h0     = (lane >> 4) * 128;          // h-half this lane covers
    const float* myq = &s_qh[q * NH + h0];
    const float* mwv = &s_wv[h0];
    const int nTilesA = (vl + 31) >> 5;            // uniform

    for (int tile = 0; tile < nTilesA; ++tile) {
        // load kh tile: 32 keys x 256 h (2048 float4, 8 per thread)
        #pragma unroll
        for (int r = 0; r < 8; ++r) {
            int i  = t + 256 * r;
            int k  = i >> 6;
            int h4 = (i & 63) * 4;
            *(float4*)&sbuf[k * STRIDE + h4] =
                *(const float4*)&khb[(tile * 32 + k) * NH + h4];
        }
        __syncthreads();

        float acc = 0.f;
        const float* myk = &sbuf[row * STRIDE + h0];
        #pragma unroll 4
        for (int h = 0; h < 128; h += 4) {
            float4 kv  = *(const float4*)&myk[h];
            float4 qv  = *(const float4*)&myq[h];    // broadcast (2 addrs/warp)
            float4 wv4 = *(const float4*)&mwv[h];    // broadcast (2 addrs/warp)
            acc += wv4.x * tanh_ap(qv.x + kv.x);
            acc += wv4.y * tanh_ap(qv.y + kv.y);
            acc += wv4.z * tanh_ap(qv.z + kv.z);
            acc += wv4.w * tanh_ap(qv.w + kv.w);
        }
        acc += __shfl_xor_sync(0xffffffffu, acc, 16);     // combine h-halves
        if (lane < 16)
            attn_s[q * NK + tile * 32 + slice * 16 + lane] = acc;
        __syncthreads();                                  // A->B vis + sbuf reuse
    }

    // ---------------- Phase B: masked softmax (even warps) ----------------
    if (slice == 0) {
        float mx = -1.0e30f;
        for (int i = 0; i < 16; i++) {
            int k = i * 32 + lane;
            float v = (k < vl) ? attn_s[q * NK + k] : -1.0e6f;
            mx = fmaxf(mx, v);
        }
        #pragma unroll
        for (int o = 16; o > 0; o >>= 1)
            mx = fmaxf(mx, __shfl_xor_sync(0xffffffffu, mx, o));

        float sum = 0.f;
        for (int i = 0; i < 16; i++) {
            int k = i * 32 + lane;
            float v = (k < vl) ? attn_s[q * NK + k] : -1.0e6f;
            float e = __expf(v - mx);                 // masked -> exact 0
            sum += e;
            attn_s[q * NK + k] = e;                   // unnormalized
        }
        #pragma unroll
        for (int o = 16; o > 0; o >>= 1)
            sum += __shfl_xor_sync(0xffffffffu, sum, o);
        if (lane == 0) s_inv[q] = 1.0f / sum;
    }
    __syncthreads();

    // ---------------- Phase C: out = attn @ values ----------------
    float4 o0 = make_float4(0.f, 0.f, 0.f, 0.f);
    const int nTilesC = (vl + 15) >> 4;
    const float* vb = &values[(b * NK) * ND];
    const int dOff = slice * 128 + lane * 4;          // this warp's d-quarter per lane

    for (int tile = 0; tile < nTilesC; ++tile) {
        // load values tile: 16 keys x 256 d (1024 float4, 4 per thread)
        #pragma unroll
        for (int r = 0; r < 4; ++r) {
            int i  = t + 256 * r;
            int k  = i >> 6;
            int h4 = (i & 63) * 4;
            *(float4*)&sbuf[k * STRIDE + h4] =
                *(const float4*)&vb[(tile * 16 + k) * ND + h4];
        }
        __syncthreads();

        #pragma unroll 4
        for (int kk = 0; kk < 16; ++kk) {
            float a = attn_s[q * NK + tile * 16 + kk];        // broadcast
            float4 v0 = *(const float4*)&sbuf[kk * STRIDE + dOff];
            o0.x += a * v0.x; o0.y += a * v0.y; o0.z += a * v0.z; o0.w += a * v0.w;
        }
        __syncthreads();                                      // readers done before next tile load
    }

    const float inv = s_inv[q];
    o0.x *= inv; o0.y *= inv; o0.z *= inv; o0.w *= inv;
    const int qrow = b * NQ + qblk * 4 + q;
    *(float4*)&out[qrow * ND + dOff] = o0;
}

// ---------------------------------------------------------------------------
extern "C" void kernel_launch(void* const* d_in, const int* in_sizes, int n_in,
                              void* d_out, int out_size)
{
    const float* queries = (const float*)d_in[0];  // (B,Q,D)
    const float* keys    = (const float*)d_in[1];  // (B,K,D)
    const float* values  = (const float*)d_in[2];  // (B,K,D)
    const float* Wq      = (const float*)d_in[3];  // (D,H)
    const float* Wk      = (const float*)d_in[4];  // (D,H)
    const float* wv      = (const float*)d_in[5];  // (H,)
    const int*   vlen    = (const int*)d_in[6];    // (B,) int32
    float* out = (float*)d_out;                    // (B,Q,D)

    (void)in_sizes; (void)n_in; (void)out_size;

    dim3 pgrid(NH / 64, (NB * NQ) / 64, 2);        // 4 x 32 x 2
    proj_kernel<<<pgrid, 256>>>(queries, Wq, keys, Wk);

    attn_kernel<<<(NB * NQ) / 4, 256>>>(values, wv, vlen, out);
}